// round 2
// baseline (speedup 1.0000x reference)
#include <cuda_runtime.h>
#include <cuda_bf16.h>

// Shapes (fixed for this problem)
#define BATCH 8
#define SEQ   2048
#define EMB   1024          // E == EI == 1024
#define MTOT  (BATCH*SEQ)   // 16384

// GEMM tiling
#define BM 128
#define BN 128
#define BK 16
#define TM 8
#define TN 8
#define NTHR 256

// ---------------- scratch (device globals; no allocation allowed) -------------
__device__ float g_h[(size_t)MTOT * EMB];   // LN1 output, reused for LN2 output
__device__ float g_q[(size_t)MTOT * EMB];
__device__ float g_k[(size_t)MTOT * EMB];
__device__ float g_v[(size_t)MTOT * EMB];
__device__ float g_o[(size_t)MTOT * EMB];   // attention output
__device__ float g_s[(size_t)BATCH * SEQ * SEQ]; // scores / attn weights (128 MiB)

// ---------------- block reductions (256 threads) ------------------------------
__device__ __forceinline__ float blockReduceSum(float v, float* sh) {
    #pragma unroll
    for (int o = 16; o > 0; o >>= 1) v += __shfl_down_sync(0xffffffffu, v, o);
    int lane = threadIdx.x & 31, wid = threadIdx.x >> 5;
    __syncthreads();
    if (lane == 0) sh[wid] = v;
    __syncthreads();
    if (wid == 0) {
        v = (lane < (NTHR / 32)) ? sh[lane] : 0.0f;
        #pragma unroll
        for (int o = 4; o > 0; o >>= 1) v += __shfl_down_sync(0xffffffffu, v, o);
        if (lane == 0) sh[0] = v;
    }
    __syncthreads();
    return sh[0];
}

__device__ __forceinline__ float blockReduceMax(float v, float* sh) {
    #pragma unroll
    for (int o = 16; o > 0; o >>= 1) v = fmaxf(v, __shfl_down_sync(0xffffffffu, v, o));
    int lane = threadIdx.x & 31, wid = threadIdx.x >> 5;
    __syncthreads();
    if (lane == 0) sh[wid] = v;
    __syncthreads();
    if (wid == 0) {
        v = (lane < (NTHR / 32)) ? sh[lane] : -1e30f;
        #pragma unroll
        for (int o = 4; o > 0; o >>= 1) v = fmaxf(v, __shfl_down_sync(0xffffffffu, v, o));
        if (lane == 0) sh[0] = v;
    }
    __syncthreads();
    return sh[0];
}

// ---------------- LayerNorm over last dim (N = 1024), one block per row -------
__global__ void __launch_bounds__(NTHR) ln_kernel(
    const float* __restrict__ x, const float* __restrict__ g,
    const float* __restrict__ b, float* __restrict__ out)
{
    __shared__ float sh[32];
    const long long row = blockIdx.x;
    const float* p = x + row * EMB;
    float* po = out + row * EMB;
    const int tid = threadIdx.x;

    float vals[4];
    float s = 0.f, s2 = 0.f;
    #pragma unroll
    for (int i = 0; i < 4; i++) {
        float v = p[tid + i * NTHR];
        vals[i] = v;
        s += v; s2 += v * v;
    }
    s  = blockReduceSum(s,  sh);
    s2 = blockReduceSum(s2, sh);
    const float mu  = s * (1.0f / EMB);
    const float var = s2 * (1.0f / EMB) - mu * mu;
    const float inv = rsqrtf(var + 1e-5f);
    #pragma unroll
    for (int i = 0; i < 4; i++) {
        int c = tid + i * NTHR;
        po[c] = (vals[i] - mu) * inv * g[c] + b[c];
    }
}

// ---------------- row softmax over N = 2048, one block per row ----------------
__global__ void __launch_bounds__(NTHR) softmax_kernel(float* __restrict__ S)
{
    __shared__ float sh[32];
    const long long row = blockIdx.x;
    float* p = S + row * (long long)SEQ;
    const int tid = threadIdx.x;

    float vals[8];
    float m = -1e30f;
    #pragma unroll
    for (int i = 0; i < 8; i++) {
        vals[i] = p[tid + i * NTHR];
        m = fmaxf(m, vals[i]);
    }
    m = blockReduceMax(m, sh);
    float s = 0.f;
    #pragma unroll
    for (int i = 0; i < 8; i++) {
        vals[i] = __expf(vals[i] - m);
        s += vals[i];
    }
    s = blockReduceSum(s, sh);
    const float inv = 1.0f / s;
    #pragma unroll
    for (int i = 0; i < 8; i++) p[tid + i * NTHR] = vals[i] * inv;
}

// ---------------- tiled SGEMM: C = A @ B (+epilogue), optional B transposed ---
// A: [M,K] row-major. TRANSB=false: B [K,N] row-major. TRANSB=true: B [N,K].
// EPI: 0 = none, 1 = +bias[n], 2 = C = 2*(acc + bias[n] + X[m,n])
// Batched via blockIdx.z with element strides sA/sB/sC. All dims divide tiles.
template<bool TRANSB, int EPI>
__global__ void __launch_bounds__(NTHR) gemm_kernel(
    const float* __restrict__ A, const float* __restrict__ Bm,
    const float* __restrict__ bias, const float* __restrict__ X,
    float* __restrict__ C, int M, int N, int K,
    long long sA, long long sB, long long sC)
{
    A  += sA * blockIdx.z;
    Bm += sB * blockIdx.z;
    C  += sC * blockIdx.z;

    const int row0 = blockIdx.y * BM;
    const int col0 = blockIdx.x * BN;

    __shared__ float As[BK][BM];
    __shared__ float Bs[BK][BN];

    const int tid = threadIdx.x;
    const int tx = tid % 16;          // -> 8 output cols
    const int ty = tid / 16;          // -> 8 output rows

    // loader indices: 128 rows x 16 cols tile as float4, 2 rows/thread
    const int aRow = tid / 4;         // 0..63
    const int aCol = (tid % 4) * 4;   // 0,4,8,12
    // NN B loader: 16 rows x 128 cols tile as float4, 2 rows/thread
    const int bRow = tid / 32;        // 0..7
    const int bCol = (tid % 32) * 4;  // 0..124

    float acc[TM][TN] = {};

    for (int k0 = 0; k0 < K; k0 += BK) {
        #pragma unroll
        for (int r = 0; r < 2; r++) {
            const int row = aRow + r * 64;
            const float4 t = *(const float4*)(A + (long long)(row0 + row) * K + k0 + aCol);
            As[aCol + 0][row] = t.x; As[aCol + 1][row] = t.y;
            As[aCol + 2][row] = t.z; As[aCol + 3][row] = t.w;
        }
        if (TRANSB) {
            #pragma unroll
            for (int r = 0; r < 2; r++) {
                const int n = aRow + r * 64; // column within BN
                const float4 t = *(const float4*)(Bm + (long long)(col0 + n) * K + k0 + aCol);
                Bs[aCol + 0][n] = t.x; Bs[aCol + 1][n] = t.y;
                Bs[aCol + 2][n] = t.z; Bs[aCol + 3][n] = t.w;
            }
        } else {
            #pragma unroll
            for (int r = 0; r < 2; r++) {
                const int kk = bRow + r * 8;
                const float4 t = *(const float4*)(Bm + (long long)(k0 + kk) * N + col0 + bCol);
                *(float4*)&Bs[kk][bCol] = t;
            }
        }
        __syncthreads();

        #pragma unroll
        for (int kk = 0; kk < BK; kk++) {
            float ra[TM], rb[TN];
            #pragma unroll
            for (int i = 0; i < TM; i++) ra[i] = As[kk][ty * TM + i];
            #pragma unroll
            for (int j = 0; j < TN; j++) rb[j] = Bs[kk][tx * TN + j];
            #pragma unroll
            for (int i = 0; i < TM; i++)
                #pragma unroll
                for (int j = 0; j < TN; j++)
                    acc[i][j] += ra[i] * rb[j];
        }
        __syncthreads();
    }

    #pragma unroll
    for (int i = 0; i < TM; i++) {
        const int row = row0 + ty * TM + i;
        #pragma unroll
        for (int j = 0; j < TN; j += 4) {
            const int col = col0 + tx * TN + j;
            float4 v = make_float4(acc[i][j], acc[i][j + 1], acc[i][j + 2], acc[i][j + 3]);
            if (EPI == 1) {
                v.x += bias[col];     v.y += bias[col + 1];
                v.z += bias[col + 2]; v.w += bias[col + 3];
            } else if (EPI == 2) {
                const float4 xb = *(const float4*)(X + (long long)row * N + col);
                v.x = 2.0f * (v.x + bias[col]     + xb.x);
                v.y = 2.0f * (v.y + bias[col + 1] + xb.y);
                v.z = 2.0f * (v.z + bias[col + 2] + xb.z);
                v.w = 2.0f * (v.w + bias[col + 3] + xb.w);
            }
            *(float4*)(C + (long long)row * N + col) = v;
        }
    }
}

// ---------------- launcher ----------------------------------------------------
extern "C" void kernel_launch(void* const* d_in, const int* in_sizes, int n_in,
                              void* d_out, int out_size)
{
    const float* x   = (const float*)d_in[0];
    const float* Wq  = (const float*)d_in[1];
    const float* bq  = (const float*)d_in[2];
    const float* Wk  = (const float*)d_in[3];
    const float* bk  = (const float*)d_in[4];
    const float* Wv  = (const float*)d_in[5];
    const float* bv  = (const float*)d_in[6];
    const float* Wfc = (const float*)d_in[7];
    const float* bfc = (const float*)d_in[8];
    const float* g1  = (const float*)d_in[9];
    const float* b1  = (const float*)d_in[10];
    const float* g2  = (const float*)d_in[11];
    const float* b2  = (const float*)d_in[12];
    float* y = (float*)d_out;

    float *h, *q, *k, *v, *s, *o;
    cudaGetSymbolAddress((void**)&h, g_h);
    cudaGetSymbolAddress((void**)&q, g_q);
    cudaGetSymbolAddress((void**)&k, g_k);
    cudaGetSymbolAddress((void**)&v, g_v);
    cudaGetSymbolAddress((void**)&s, g_s);
    cudaGetSymbolAddress((void**)&o, g_o);

    const long long strQKV = (long long)SEQ * EMB;   // per-batch stride in q/k/v
    const long long strS   = (long long)SEQ * SEQ;   // per-batch stride in scores

    // 1) h = LN(x; g1,b1)
    ln_kernel<<<MTOT, NTHR>>>(x, g1, b1, h);

    // 2) q,k,v = h @ W* + b*
    {
        dim3 grid(EMB / BN, MTOT / BM, 1);
        gemm_kernel<false, 1><<<grid, NTHR>>>(h, Wq, bq, nullptr, q, MTOT, EMB, EMB, 0, 0, 0);
        gemm_kernel<false, 1><<<grid, NTHR>>>(h, Wk, bk, nullptr, k, MTOT, EMB, EMB, 0, 0, 0);
        gemm_kernel<false, 1><<<grid, NTHR>>>(h, Wv, bv, nullptr, v, MTOT, EMB, EMB, 0, 0, 0);
    }

    // 3) s[b] = q[b] @ k[b]^T   (NT, batched)
    {
        dim3 grid(SEQ / BN, SEQ / BM, BATCH);
        gemm_kernel<true, 0><<<grid, NTHR>>>(q, k, nullptr, nullptr, s,
                                             SEQ, SEQ, EMB, strQKV, strQKV, strS);
    }

    // 4) row softmax over keys
    softmax_kernel<<<MTOT, NTHR>>>(s);

    // 5) o[b] = s[b] @ v[b]     (NN, batched)
    {
        dim3 grid(EMB / BN, SEQ / BM, BATCH);
        gemm_kernel<false, 0><<<grid, NTHR>>>(s, v, nullptr, nullptr, o,
                                              SEQ, EMB, SEQ, strS, strQKV, strQKV);
    }

    // 6) h = LN(o; g2,b2)   (reuse h)
    ln_kernel<<<MTOT, NTHR>>>(o, g2, b2, h);

    // 7) y = 2*(h @ Wfc + bfc + x)
    {
        dim3 grid(EMB / BN, MTOT / BM, 1);
        gemm_kernel<false, 2><<<grid, NTHR>>>(h, Wfc, bfc, x, y, MTOT, EMB, EMB, 0, 0, 0);
    }
}